// round 7
// baseline (speedup 1.0000x reference)
#include <cuda_runtime.h>

#define BB  64
#define INN 512
#define HH  512
#define HID 16

// ---------------- packed f32x2 helpers (Blackwell sm_100+) ----------------
typedef unsigned long long u64;

static __device__ __forceinline__ u64 f2_fma(u64 a, u64 b, u64 c) {
    u64 r;
    asm("fma.rn.f32x2 %0, %1, %2, %3;" : "=l"(r) : "l"(a), "l"(b), "l"(c));
    return r;
}
static __device__ __forceinline__ u64 f2_add(u64 a, u64 b) {
    u64 r;
    asm("add.rn.f32x2 %0, %1, %2;" : "=l"(r) : "l"(a), "l"(b));
    return r;
}
static __device__ __forceinline__ u64 f2_pack(float x, float y) {
    u64 r;
    asm("mov.b64 %0, {%1, %2};" : "=l"(r) : "f"(x), "f"(y));
    return r;
}
static __device__ __forceinline__ float2 f2_unpack(u64 v) {
    float2 r;
    asm("mov.b64 {%0, %1}, %2;" : "=f"(r.x), "=f"(r.y) : "l"(v));
    return r;
}
// relu: pack/unpack are register aliasing (free); 2x FMNMX on the alu pipe.
// (There is NO packed max.f32x2 in PTX -- only add/mul/fma.rn.f32x2.)
static __device__ __forceinline__ u64 f2_relu(u64 v) {
    float2 t = f2_unpack(v);
    return f2_pack(fmaxf(t.x, 0.0f), fmaxf(t.y, 0.0f));
}

// ---------------- fused kernel ----------------
// out[i,j] = (1/B) * sum_b sum_k relu(pre[b,i]*u_k + post[b,j]*v_k + w_ij*t_k + b1_k) * W2_k + b2
//
// Thread tile: 1 i x 2 j. Block: 128 threads = 64 (tj) x 2 (ti).
// Grid: (512/128, 512/2) = (4, 256) = 1024 blocks.
//
// Register budget is the wave-structure lever: k is processed in FOUR chunks
// of 2 packed pairs so only 20 regs of constants are live. Target <=64 regs
// (__launch_bounds__(128, 8)) -> 8 blocks/SM capacity -> all 1024 blocks
// resident in ONE wave (round 5 at 76 regs ran a 2-wave straggler tail).
// acc[jj][kp] gives 4 independent chains; b-loop prefetches next b.
__global__ __launch_bounds__(128, 8)
void plasticity_fused(const float* __restrict__ pre,
                      const float* __restrict__ post,
                      const float* __restrict__ weight,
                      const float* __restrict__ W1,
                      const float* __restrict__ b1,
                      const float* __restrict__ W2,
                      const float* __restrict__ b2,
                      float* __restrict__ out) {
    const int tj = threadIdx.x & 63;       // 0..63
    const int ti = threadIdx.x >> 6;       // 0..1 (warp-uniform)
    const int i  = blockIdx.y * 2 + ti;
    const int j0 = blockIdx.x * 128 + tj * 2;

    const float* pre_i  = pre  + i;        // stride INN over b
    const float* post_j = post + j0;       // stride HH  over b

    // w_ij for this thread's 2 j, broadcast into both f32x2 lanes.
    float2 wv = *reinterpret_cast<const float2*>(&weight[(size_t)i * HH + j0]);
    const u64 wij0 = f2_pack(wv.x, wv.x);
    const u64 wij1 = f2_pack(wv.y, wv.y);

    // 2 jj x 2 kp accumulator chains, persist across chunks.
    u64 acc[2][2] = { {0ull, 0ull}, {0ull, 0ull} };

#pragma unroll 1
    for (int chunk = 0; chunk < 4; ++chunk) {
        const int k0 = chunk * 4;          // 4 k (= 2 packed pairs) per chunk
        // Packed constants for this chunk: 5 arrays x 2 pairs = 20 regs.
        u64 u2[2], v2[2], b12[2], t2[2], w2p[2];
#pragma unroll
        for (int kp = 0; kp < 2; ++kp) {
            int ka = k0 + 2 * kp, kb = ka + 1;
            u2[kp]  = f2_pack(W1[ka * 3 + 0], W1[kb * 3 + 0]);
            v2[kp]  = f2_pack(W1[ka * 3 + 1], W1[kb * 3 + 1]);
            t2[kp]  = f2_pack(W1[ka * 3 + 2], W1[kb * 3 + 2]);
            b12[kp] = f2_pack(b1[ka], b1[kb]);
            w2p[kp] = f2_pack(W2[ka], W2[kb]);
        }

        // Software pipeline: prefetch b=0, then in-loop prefetch b+1 (wrapped).
        float  pf_pre  = pre_i[0];
        float2 pf_post = *reinterpret_cast<const float2*>(post_j);

#pragma unroll 1
        for (int b = 0; b < BB; ++b) {
            const float  cp = pf_pre;
            const float2 cq = pf_post;
            const int bn = (b + 1) & (BB - 1);   // wraps to 0 (harmless reload)
            pf_pre  = pre_i[(size_t)bn * INN];
            pf_post = *reinterpret_cast<const float2*>(&post_j[(size_t)bn * HH]);

            const u64 pre2  = f2_pack(cp, cp);
            const u64 postA = f2_pack(cq.x, cq.x);
            const u64 postB = f2_pack(cq.y, cq.y);

            // a[kp] = pre_i * u_k + b1_k  (shared by both jj)
            u64 a0 = f2_fma(pre2, u2[0], b12[0]);
            u64 a1 = f2_fma(pre2, u2[1], b12[1]);

            // jj = 0
            u64 x00 = f2_fma(postA, v2[0], a0);
            u64 x01 = f2_fma(postA, v2[1], a1);
            x00 = f2_fma(wij0, t2[0], x00);
            x01 = f2_fma(wij0, t2[1], x01);
            acc[0][0] = f2_fma(f2_relu(x00), w2p[0], acc[0][0]);
            acc[0][1] = f2_fma(f2_relu(x01), w2p[1], acc[0][1]);
            // jj = 1
            u64 x10 = f2_fma(postB, v2[0], a0);
            u64 x11 = f2_fma(postB, v2[1], a1);
            x10 = f2_fma(wij1, t2[0], x10);
            x11 = f2_fma(wij1, t2[1], x11);
            acc[1][0] = f2_fma(f2_relu(x10), w2p[0], acc[1][0]);
            acc[1][1] = f2_fma(f2_relu(x11), w2p[1], acc[1][1]);
        }
    }

    const float inv_b = 1.0f / (float)BB;
    const float bias2 = b2[0];
    float2 res;
#pragma unroll
    for (int jj = 0; jj < 2; ++jj) {
        float2 s = f2_unpack(f2_add(acc[jj][0], acc[jj][1]));
        (&res.x)[jj] = fmaf(s.x + s.y, inv_b, bias2);
    }
    *reinterpret_cast<float2*>(&out[(size_t)i * HH + j0]) = res;
}

// ---------------- launch ----------------
extern "C" void kernel_launch(void* const* d_in, const int* in_sizes, int n_in,
                              void* d_out, int out_size) {
    const float* pre    = (const float*)d_in[0];
    const float* post   = (const float*)d_in[1];
    const float* weight = (const float*)d_in[2];
    const float* W1     = (const float*)d_in[3];
    const float* b1     = (const float*)d_in[4];
    const float* W2     = (const float*)d_in[5];
    const float* b2     = (const float*)d_in[6];
    float* out = (float*)d_out;

    plasticity_fused<<<dim3(HH / 128, INN / 2), 128>>>(
        pre, post, weight, W1, b1, W2, b2, out);
}

// round 9
// speedup vs baseline: 1.1985x; 1.1985x over previous
#include <cuda_runtime.h>

#define BB  64
#define INN 512
#define HH  512
#define HID 16

// ---------------- packed f32x2 helpers (Blackwell sm_100+) ----------------
typedef unsigned long long u64;

static __device__ __forceinline__ u64 f2_fma(u64 a, u64 b, u64 c) {
    u64 r;
    asm("fma.rn.f32x2 %0, %1, %2, %3;" : "=l"(r) : "l"(a), "l"(b), "l"(c));
    return r;
}
static __device__ __forceinline__ u64 f2_add(u64 a, u64 b) {
    u64 r;
    asm("add.rn.f32x2 %0, %1, %2;" : "=l"(r) : "l"(a), "l"(b));
    return r;
}
static __device__ __forceinline__ u64 f2_pack(float x, float y) {
    u64 r;
    asm("mov.b64 %0, {%1, %2};" : "=l"(r) : "f"(x), "f"(y));
    return r;
}
static __device__ __forceinline__ float2 f2_unpack(u64 v) {
    float2 r;
    asm("mov.b64 {%0, %1}, %2;" : "=f"(r.x), "=f"(r.y) : "l"(v));
    return r;
}
// relu: pack/unpack are register aliasing (free); 2x FMNMX on the alu pipe.
// (No packed max.f32x2 exists in PTX -- only add/mul/fma.rn.f32x2.)
static __device__ __forceinline__ u64 f2_relu(u64 v) {
    float2 t = f2_unpack(v);
    return f2_pack(fmaxf(t.x, 0.0f), fmaxf(t.y, 0.0f));
}

// ---------------- fused kernel ----------------
// out[i,j] = (1/B) * sum_b sum_k relu(pre[b,i]*u_k + post[b,j]*v_k + w_ij*t_k + b1_k) * W2_k + b2
//
// (Re-bench of round-8 kernel: previous run died to container infra, not the kernel.)
//
// d-trick: w_ij*t_k + b1_k is loop-invariant PER THREAD -> precompute
// d[jj][kp] once per half; inner body is 2 chained fma + relu + acc-fma
// per (jj,kp) instead of 3 fma (round 5) -- same registers, -4 FFMA2/half-b.
//
// Thread tile: 1 i x 2 j. Block: 128 threads = 64 (tj) x 2 (ti).
// Grid: (4, 256) = 1024 blocks. __launch_bounds__(128, 7): reg budget 73,
// capacity 148*7 = 1036 >= 1024 -> ONE wave (round 7's occupancy win)
// at half-split overhead (round 5's low instruction count).
__global__ __launch_bounds__(128, 7)
void plasticity_fused(const float* __restrict__ pre,
                      const float* __restrict__ post,
                      const float* __restrict__ weight,
                      const float* __restrict__ W1,
                      const float* __restrict__ b1,
                      const float* __restrict__ W2,
                      const float* __restrict__ b2,
                      float* __restrict__ out) {
    const int tj = threadIdx.x & 63;       // 0..63
    const int ti = threadIdx.x >> 6;       // 0..1 (warp-uniform)
    const int i  = blockIdx.y * 2 + ti;
    const int j0 = blockIdx.x * 128 + tj * 2;

    const float* pre_i  = pre  + i;        // stride INN over b
    const float* post_j = post + j0;       // stride HH  over b

    // w_ij for this thread's 2 j, broadcast into both f32x2 lanes.
    float2 wv = *reinterpret_cast<const float2*>(&weight[(size_t)i * HH + j0]);
    const u64 wij0 = f2_pack(wv.x, wv.x);
    const u64 wij1 = f2_pack(wv.y, wv.y);

    // 2 jj x 2 kp-parity accumulator chains, persist across halves.
    u64 acc[2][2] = { {0ull, 0ull}, {0ull, 0ull} };

#pragma unroll 1
    for (int half = 0; half < 2; ++half) {
        const int k0 = half * 8;
        // Live constants this half: u2,v2,w2p + folded d0,d1 = 40 regs.
        u64 u2[4], v2[4], w2p[4], d0[4], d1[4];
#pragma unroll
        for (int kp = 0; kp < 4; ++kp) {
            int ka = k0 + 2 * kp, kb = ka + 1;
            u2[kp]  = f2_pack(W1[ka * 3 + 0], W1[kb * 3 + 0]);
            v2[kp]  = f2_pack(W1[ka * 3 + 1], W1[kb * 3 + 1]);
            u64 t2  = f2_pack(W1[ka * 3 + 2], W1[kb * 3 + 2]);
            u64 b12 = f2_pack(b1[ka], b1[kb]);
            w2p[kp] = f2_pack(W2[ka], W2[kb]);
            d0[kp]  = f2_fma(wij0, t2, b12);   // w_i,j0 * t_k + b1_k
            d1[kp]  = f2_fma(wij1, t2, b12);   // w_i,j0+1 * t_k + b1_k
        }

        // Software pipeline: prefetch b=0, then in-loop prefetch b+1 (wrapped).
        float  pf_pre  = pre_i[0];
        float2 pf_post = *reinterpret_cast<const float2*>(post_j);

#pragma unroll 1
        for (int b = 0; b < BB; ++b) {
            const float  cp = pf_pre;
            const float2 cq = pf_post;
            const int bn = (b + 1) & (BB - 1);   // wraps to 0 (harmless reload)
            pf_pre  = pre_i[(size_t)bn * INN];
            pf_post = *reinterpret_cast<const float2*>(&post_j[(size_t)bn * HH]);

            const u64 pre2  = f2_pack(cp, cp);
            const u64 postA = f2_pack(cq.x, cq.x);
            const u64 postB = f2_pack(cq.y, cq.y);

#pragma unroll
            for (int kp = 0; kp < 4; ++kp) {
                u64 x0 = f2_fma(postA, v2[kp], d0[kp]);   // post*v + (w*t+b1)
                x0 = f2_fma(pre2, u2[kp], x0);            // + pre*u
                acc[0][kp & 1] = f2_fma(f2_relu(x0), w2p[kp], acc[0][kp & 1]);

                u64 x1 = f2_fma(postB, v2[kp], d1[kp]);
                x1 = f2_fma(pre2, u2[kp], x1);
                acc[1][kp & 1] = f2_fma(f2_relu(x1), w2p[kp], acc[1][kp & 1]);
            }
        }
    }

    const float inv_b = 1.0f / (float)BB;
    const float bias2 = b2[0];
    float2 res;
#pragma unroll
    for (int jj = 0; jj < 2; ++jj) {
        float2 s = f2_unpack(f2_add(acc[jj][0], acc[jj][1]));
        (&res.x)[jj] = fmaf(s.x + s.y, inv_b, bias2);
    }
    *reinterpret_cast<float2*>(&out[(size_t)i * HH + j0]) = res;
}

// ---------------- launch ----------------
extern "C" void kernel_launch(void* const* d_in, const int* in_sizes, int n_in,
                              void* d_out, int out_size) {
    const float* pre    = (const float*)d_in[0];
    const float* post   = (const float*)d_in[1];
    const float* weight = (const float*)d_in[2];
    const float* W1     = (const float*)d_in[3];
    const float* b1     = (const float*)d_in[4];
    const float* W2     = (const float*)d_in[5];
    const float* b2     = (const float*)d_in[6];
    float* out = (float*)d_out;

    plasticity_fused<<<dim3(HH / 128, INN / 2), 128>>>(
        pre, post, weight, W1, b1, W2, b2, out);
}

// round 10
// speedup vs baseline: 1.2180x; 1.0163x over previous
#include <cuda_runtime.h>

#define BB  64
#define INN 512
#define HH  512
#define HID 16

// ---------------- packed f32x2 helpers (Blackwell sm_100+) ----------------
typedef unsigned long long u64;

static __device__ __forceinline__ u64 f2_fma(u64 a, u64 b, u64 c) {
    u64 r;
    asm("fma.rn.f32x2 %0, %1, %2, %3;" : "=l"(r) : "l"(a), "l"(b), "l"(c));
    return r;
}
static __device__ __forceinline__ u64 f2_add(u64 a, u64 b) {
    u64 r;
    asm("add.rn.f32x2 %0, %1, %2;" : "=l"(r) : "l"(a), "l"(b));
    return r;
}
static __device__ __forceinline__ u64 f2_pack(float x, float y) {
    u64 r;
    asm("mov.b64 %0, {%1, %2};" : "=l"(r) : "f"(x), "f"(y));
    return r;
}
static __device__ __forceinline__ float2 f2_unpack(u64 v) {
    float2 r;
    asm("mov.b64 {%0, %1}, %2;" : "=f"(r.x), "=f"(r.y) : "l"(v));
    return r;
}
// relu: pack/unpack are register aliasing (free); 2x FMNMX on the alu pipe.
// (No packed max.f32x2 exists in PTX -- only add/mul/fma.rn.f32x2.)
static __device__ __forceinline__ u64 f2_relu(u64 v) {
    float2 t = f2_unpack(v);
    return f2_pack(fmaxf(t.x, 0.0f), fmaxf(t.y, 0.0f));
}

// ---------------- fused kernel ----------------
// out[i,j] = (1/B) * sum_b sum_k relu(pre[b,i]*u_k + post[b,j]*v_k + w_ij*t_k + b1_k) * W2_k + b2
//
// Structure proven through R9: 1i x 2j thread tile, k in two halves with the
// d-trick (d = w_ij*t_k + b1_k folded per thread), __launch_bounds__(128,7)
// -> <=73 regs -> 28 warps/SM RF ceiling, 1024 blocks in ONE wave.
//
// R10 change: occupancy is RF-capped, warps idle in RAW waits (issue 47.7%).
// Unroll b by 2: both b-iterations' loads batch at the top (one scoreboard
// wait per 2 b), two full independent math bodies interleave to cover the
// 4-cyc fma latency, and loop overhead halves. Wrap-prefetch removed.
__global__ __launch_bounds__(128, 7)
void plasticity_fused(const float* __restrict__ pre,
                      const float* __restrict__ post,
                      const float* __restrict__ weight,
                      const float* __restrict__ W1,
                      const float* __restrict__ b1,
                      const float* __restrict__ W2,
                      const float* __restrict__ b2,
                      float* __restrict__ out) {
    const int tj = threadIdx.x & 63;       // 0..63
    const int ti = threadIdx.x >> 6;       // 0..1 (warp-uniform)
    const int i  = blockIdx.y * 2 + ti;
    const int j0 = blockIdx.x * 128 + tj * 2;

    // w_ij for this thread's 2 j (kept as scalars; packed in half-prologue).
    const float2 wv = *reinterpret_cast<const float2*>(&weight[(size_t)i * HH + j0]);

    // 2 jj x 2 kp-parity accumulator chains, persist across halves.
    u64 acc[2][2] = { {0ull, 0ull}, {0ull, 0ull} };

#pragma unroll 1
    for (int half = 0; half < 2; ++half) {
        const int k0 = half * 8;
        // Live constants this half: u2,v2,w2p + folded d0,d1 = 40 regs.
        u64 u2[4], v2[4], w2p[4], d0[4], d1[4];
        {
            const u64 wij0 = f2_pack(wv.x, wv.x);
            const u64 wij1 = f2_pack(wv.y, wv.y);
#pragma unroll
            for (int kp = 0; kp < 4; ++kp) {
                int ka = k0 + 2 * kp, kb = ka + 1;
                u2[kp]  = f2_pack(W1[ka * 3 + 0], W1[kb * 3 + 0]);
                v2[kp]  = f2_pack(W1[ka * 3 + 1], W1[kb * 3 + 1]);
                u64 t2  = f2_pack(W1[ka * 3 + 2], W1[kb * 3 + 2]);
                u64 b12 = f2_pack(b1[ka], b1[kb]);
                w2p[kp] = f2_pack(W2[ka], W2[kb]);
                d0[kp]  = f2_fma(wij0, t2, b12);   // w_i,j0   * t_k + b1_k
                d1[kp]  = f2_fma(wij1, t2, b12);   // w_i,j0+1 * t_k + b1_k
            }
        }

        const float* pp = pre + i;             // advances 2*INN per iter
        const float* qq = post + j0;           // advances 2*HH per iter

#pragma unroll 1
        for (int b = 0; b < BB; b += 2) {
            // Batch all 4 loads up front (one scoreboard wait per 2 b).
            const float  cp0 = pp[0];
            const float  cp1 = pp[INN];
            const float2 cq0 = *reinterpret_cast<const float2*>(qq);
            const float2 cq1 = *reinterpret_cast<const float2*>(qq + HH);
            pp += 2 * INN;
            qq += 2 * HH;

            // ---- b even ----
            {
                const u64 pre2  = f2_pack(cp0, cp0);
                const u64 postA = f2_pack(cq0.x, cq0.x);
                const u64 postB = f2_pack(cq0.y, cq0.y);
#pragma unroll
                for (int kp = 0; kp < 4; ++kp) {
                    u64 x0 = f2_fma(postA, v2[kp], d0[kp]);
                    x0 = f2_fma(pre2, u2[kp], x0);
                    acc[0][kp & 1] = f2_fma(f2_relu(x0), w2p[kp], acc[0][kp & 1]);

                    u64 x1 = f2_fma(postB, v2[kp], d1[kp]);
                    x1 = f2_fma(pre2, u2[kp], x1);
                    acc[1][kp & 1] = f2_fma(f2_relu(x1), w2p[kp], acc[1][kp & 1]);
                }
            }
            // ---- b odd ----
            {
                const u64 pre2  = f2_pack(cp1, cp1);
                const u64 postA = f2_pack(cq1.x, cq1.x);
                const u64 postB = f2_pack(cq1.y, cq1.y);
#pragma unroll
                for (int kp = 0; kp < 4; ++kp) {
                    u64 x0 = f2_fma(postA, v2[kp], d0[kp]);
                    x0 = f2_fma(pre2, u2[kp], x0);
                    acc[0][kp & 1] = f2_fma(f2_relu(x0), w2p[kp], acc[0][kp & 1]);

                    u64 x1 = f2_fma(postB, v2[kp], d1[kp]);
                    x1 = f2_fma(pre2, u2[kp], x1);
                    acc[1][kp & 1] = f2_fma(f2_relu(x1), w2p[kp], acc[1][kp & 1]);
                }
            }
        }
    }

    const float inv_b = 1.0f / (float)BB;
    const float bias2 = b2[0];
    float2 res;
#pragma unroll
    for (int jj = 0; jj < 2; ++jj) {
        float2 s = f2_unpack(f2_add(acc[jj][0], acc[jj][1]));
        (&res.x)[jj] = fmaf(s.x + s.y, inv_b, bias2);
    }
    *reinterpret_cast<float2*>(&out[(size_t)i * HH + j0]) = res;
}

// ---------------- launch ----------------
extern "C" void kernel_launch(void* const* d_in, const int* in_sizes, int n_in,
                              void* d_out, int out_size) {
    const float* pre    = (const float*)d_in[0];
    const float* post   = (const float*)d_in[1];
    const float* weight = (const float*)d_in[2];
    const float* W1     = (const float*)d_in[3];
    const float* b1     = (const float*)d_in[4];
    const float* W2     = (const float*)d_in[5];
    const float* b2     = (const float*)d_in[6];
    float* out = (float*)d_out;

    plasticity_fused<<<dim3(HH / 128, INN / 2), 128>>>(
        pre, post, weight, W1, b1, W2, b2, out);
}

// round 11
// speedup vs baseline: 1.2709x; 1.0434x over previous
#include <cuda_runtime.h>

#define BB  64
#define INN 512
#define HH  512
#define HID 16

// ---------------- packed f32x2 helpers (Blackwell sm_100+) ----------------
typedef unsigned long long u64;

static __device__ __forceinline__ u64 f2_fma(u64 a, u64 b, u64 c) {
    u64 r;
    asm("fma.rn.f32x2 %0, %1, %2, %3;" : "=l"(r) : "l"(a), "l"(b), "l"(c));
    return r;
}
static __device__ __forceinline__ u64 f2_add(u64 a, u64 b) {
    u64 r;
    asm("add.rn.f32x2 %0, %1, %2;" : "=l"(r) : "l"(a), "l"(b));
    return r;
}
static __device__ __forceinline__ u64 f2_pack(float x, float y) {
    u64 r;
    asm("mov.b64 %0, {%1, %2};" : "=l"(r) : "f"(x), "f"(y));
    return r;
}
static __device__ __forceinline__ float2 f2_unpack(u64 v) {
    float2 r;
    asm("mov.b64 {%0, %1}, %2;" : "=f"(r.x), "=f"(r.y) : "l"(v));
    return r;
}
// relu: pack/unpack are register aliasing (free); 2x FMNMX on the alu pipe.
// (No packed max.f32x2 exists in PTX -- only add/mul/fma.rn.f32x2.)
static __device__ __forceinline__ u64 f2_relu(u64 v) {
    float2 t = f2_unpack(v);
    return f2_pack(fmaxf(t.x, 0.0f), fmaxf(t.y, 0.0f));
}

// ---------------- fused kernel ----------------
// out[i,j] = (1/B) * sum_b sum_k relu(pre[b,i]*u_k + post[b,j]*v_k + w_ij*t_k + b1_k) * W2_k + b2
//
// R11 theory: every prior variant pinned issue at ~50% because 40 regs of
// k-half constants + unrolled chain temps cannot coexist under the register
// budget -- ptxas serializes the chains and RAW stalls dominate.
// Fix: k-QUARTER chunks (20 const regs: u2,v2,w2p,d0,d1 x 2 pairs) combined
// with the b x 2 unroll (batched loads, low loop overhead). Estimated live
// regs ~58 -> __launch_bounds__(128,8) (<=64): 32-warp/SM RF ceiling, ONE
// wave (8*148=1184 >= 1024 blocks), and the 8 chains/iter of temps FIT.
// acc[jj][kp] direct: 4 independent accumulator chains across all chunks.
__global__ __launch_bounds__(128, 8)
void plasticity_fused(const float* __restrict__ pre,
                      const float* __restrict__ post,
                      const float* __restrict__ weight,
                      const float* __restrict__ W1,
                      const float* __restrict__ b1,
                      const float* __restrict__ W2,
                      const float* __restrict__ b2,
                      float* __restrict__ out) {
    const int tj = threadIdx.x & 63;       // 0..63
    const int ti = threadIdx.x >> 6;       // 0..1 (warp-uniform)
    const int i  = blockIdx.y * 2 + ti;
    const int j0 = blockIdx.x * 128 + tj * 2;

    // w_ij for this thread's 2 j.
    const float2 wv = *reinterpret_cast<const float2*>(&weight[(size_t)i * HH + j0]);

    // 2 jj x 2 kp accumulator chains, persist across chunks.
    u64 acc[2][2] = { {0ull, 0ull}, {0ull, 0ull} };

#pragma unroll 1
    for (int chunk = 0; chunk < 4; ++chunk) {
        const int k0 = chunk * 4;          // 4 k = 2 packed pairs per chunk
        // Live constants this chunk: 5 arrays x 2 pairs = 20 regs.
        u64 u2[2], v2[2], w2p[2], d0[2], d1[2];
        {
            const u64 wij0 = f2_pack(wv.x, wv.x);
            const u64 wij1 = f2_pack(wv.y, wv.y);
#pragma unroll
            for (int kp = 0; kp < 2; ++kp) {
                int ka = k0 + 2 * kp, kb = ka + 1;
                u2[kp]  = f2_pack(W1[ka * 3 + 0], W1[kb * 3 + 0]);
                v2[kp]  = f2_pack(W1[ka * 3 + 1], W1[kb * 3 + 1]);
                u64 t2  = f2_pack(W1[ka * 3 + 2], W1[kb * 3 + 2]);
                u64 b12 = f2_pack(b1[ka], b1[kb]);
                w2p[kp] = f2_pack(W2[ka], W2[kb]);
                d0[kp]  = f2_fma(wij0, t2, b12);   // w_i,j0   * t_k + b1_k
                d1[kp]  = f2_fma(wij1, t2, b12);   // w_i,j0+1 * t_k + b1_k
            }
        }

        const float* pp = pre + i;             // advances 2*INN per iter
        const float* qq = post + j0;           // advances 2*HH per iter

#pragma unroll 1
        for (int b = 0; b < BB; b += 2) {
            // Batch all 4 loads up front (one scoreboard wait per 2 b).
            const float  cp0 = pp[0];
            const float  cp1 = pp[INN];
            const float2 cq0 = *reinterpret_cast<const float2*>(qq);
            const float2 cq1 = *reinterpret_cast<const float2*>(qq + HH);
            pp += 2 * INN;
            qq += 2 * HH;

            // ---- b even ----
            {
                const u64 pre2  = f2_pack(cp0, cp0);
                const u64 postA = f2_pack(cq0.x, cq0.x);
                const u64 postB = f2_pack(cq0.y, cq0.y);
#pragma unroll
                for (int kp = 0; kp < 2; ++kp) {
                    u64 x0 = f2_fma(postA, v2[kp], d0[kp]);
                    x0 = f2_fma(pre2, u2[kp], x0);
                    acc[0][kp] = f2_fma(f2_relu(x0), w2p[kp], acc[0][kp]);

                    u64 x1 = f2_fma(postB, v2[kp], d1[kp]);
                    x1 = f2_fma(pre2, u2[kp], x1);
                    acc[1][kp] = f2_fma(f2_relu(x1), w2p[kp], acc[1][kp]);
                }
            }
            // ---- b odd ----
            {
                const u64 pre2  = f2_pack(cp1, cp1);
                const u64 postA = f2_pack(cq1.x, cq1.x);
                const u64 postB = f2_pack(cq1.y, cq1.y);
#pragma unroll
                for (int kp = 0; kp < 2; ++kp) {
                    u64 x0 = f2_fma(postA, v2[kp], d0[kp]);
                    x0 = f2_fma(pre2, u2[kp], x0);
                    acc[0][kp] = f2_fma(f2_relu(x0), w2p[kp], acc[0][kp]);

                    u64 x1 = f2_fma(postB, v2[kp], d1[kp]);
                    x1 = f2_fma(pre2, u2[kp], x1);
                    acc[1][kp] = f2_fma(f2_relu(x1), w2p[kp], acc[1][kp]);
                }
            }
        }
    }

    const float inv_b = 1.0f / (float)BB;
    const float bias2 = b2[0];
    float2 res;
#pragma unroll
    for (int jj = 0; jj < 2; ++jj) {
        float2 s = f2_unpack(f2_add(acc[jj][0], acc[jj][1]));
        (&res.x)[jj] = fmaf(s.x + s.y, inv_b, bias2);
    }
    *reinterpret_cast<float2*>(&out[(size_t)i * HH + j0]) = res;
}

// ---------------- launch ----------------
extern "C" void kernel_launch(void* const* d_in, const int* in_sizes, int n_in,
                              void* d_out, int out_size) {
    const float* pre    = (const float*)d_in[0];
    const float* post   = (const float*)d_in[1];
    const float* weight = (const float*)d_in[2];
    const float* W1     = (const float*)d_in[3];
    const float* b1     = (const float*)d_in[4];
    const float* W2     = (const float*)d_in[5];
    const float* b2     = (const float*)d_in[6];
    float* out = (float*)d_out;

    plasticity_fused<<<dim3(HH / 128, INN / 2), 128>>>(
        pre, post, weight, W1, b1, W2, b2, out);
}